// round 2
// baseline (speedup 1.0000x reference)
#include <cuda_runtime.h>
#include <math.h>

#define NNODES 65535
#define IN_DIM 300
#define MEM 256
#define IOU 768          // 3*MEM
#define XCOLS 1024       // 768 iou + 256 fx
#define GCOLS 1280       // 768 iou-rec + 256 f_l + 256 f_r
#define NINTERNAL 32767
#define LEAF_START 32767
#define NLEAF 32768

// Scratch (allocation-free rule: __device__ globals)
__device__ float g_P[(size_t)NNODES * XCOLS];   // x-projections (+folded biases)
__device__ float g_G[(size_t)16384 * GCOLS];    // per-level recurrent GEMM out
__device__ float g_bias[XCOLS];

__device__ __forceinline__ float sigmoidf_(float x) { return 1.0f / (1.0f + expf(-x)); }

__global__ void bias_prep(const float* __restrict__ b_ioux, const float* __restrict__ b_iouh,
                          const float* __restrict__ b_fx, const float* __restrict__ b_fh) {
    int j = threadIdx.x + blockIdx.x * blockDim.x;
    if (j < IOU)        g_bias[j] = b_ioux[j] + b_iouh[j];
    else if (j < XCOLS) g_bias[j] = b_fx[j - IOU] + b_fh[j - IOU];
}

// ---------------------------------------------------------------------------
// Tiled SGEMM: C[M, cols] = A[M,K] * W^T (+ bias for MODE 0)
// MODE 0: A = inputs (lda=IN_DIM); W rows: col<768 -> W0(W_ioux), else W1(W_fx); C = g_P
// MODE 1: A gathered from h by column region:
//         cols [0,768)    : hsum = h[2n+1] + h[2n+2], W = W_iouh (W0)
//         cols [768,1024) : h[2n+1],                  W = W_fh  (W1)
//         cols [1024,1280): h[2n+2],                  W = W_fh  (W1)
//         C = g_G (level-local rows)
// ---------------------------------------------------------------------------
#define BM 128
#define BN 128
#define BK 16
#define TM 8
#define TN 8

template<int MODE>
__global__ __launch_bounds__(256, 2)
void gemm_kernel(int M, int K, int colOff,
                 const float* __restrict__ A, int lda,
                 const float* __restrict__ hbase, int level_start,
                 const float* __restrict__ W0, const float* __restrict__ W1)
{
    __shared__ float As[BK][BM];
    __shared__ float Bs[BK][BN];

    const int tid = threadIdx.x;
    const int tx = tid & 15;
    const int ty = tid >> 4;
    const int m0 = blockIdx.y * BM;
    const int colBase = colOff + blockIdx.x * BN;

    float* Cbase = (MODE == 0) ? g_P : g_G;
    const int ldc = (MODE == 0) ? XCOLS : GCOLS;

    const float* Wsrc;
    int wrow0;
    int region = 0;   // only used by MODE 1
    if (MODE == 0) {
        if (colBase < IOU) { Wsrc = W0; wrow0 = colBase; }
        else               { Wsrc = W1; wrow0 = colBase - IOU; }
    } else {
        if (colBase < IOU)            { Wsrc = W0; wrow0 = colBase;             region = 0; }
        else if (colBase < IOU + MEM) { Wsrc = W1; wrow0 = colBase - IOU;       region = 1; }
        else                          { Wsrc = W1; wrow0 = colBase - IOU - MEM; region = 2; }
    }

    float acc[TM][TN];
    #pragma unroll
    for (int i = 0; i < TM; i++)
        #pragma unroll
        for (int j = 0; j < TN; j++) acc[i][j] = 0.0f;

    const int nIter = (K + BK - 1) / BK;
    for (int it = 0; it < nIter; it++) {
        const int k0 = it * BK;

        // ---- load A tile (transposed into As[k][m]) ----
        #pragma unroll
        for (int ld = 0; ld < 2; ld++) {
            int e   = tid * 2 + ld;          // 0..511
            int row = e >> 2;                // 0..127
            int kq  = (e & 3) << 2;          // 0,4,8,12
            int k   = k0 + kq;
            float4 av = make_float4(0.f, 0.f, 0.f, 0.f);
            int gm = m0 + row;
            if (gm < M) {
                if (MODE == 0) {
                    if (k + 3 < K) {
                        av = *reinterpret_cast<const float4*>(A + (size_t)gm * lda + k);
                    } else {
                        float t[4] = {0.f, 0.f, 0.f, 0.f};
                        #pragma unroll
                        for (int q = 0; q < 4; q++)
                            if (k + q < K) t[q] = A[(size_t)gm * lda + k + q];
                        av = make_float4(t[0], t[1], t[2], t[3]);
                    }
                } else {
                    size_t node = (size_t)level_start + gm;
                    if (region != 2) {
                        av = *reinterpret_cast<const float4*>(hbase + (2 * node + 1) * MEM + k);
                    }
                    if (region != 1) {
                        float4 r4 = *reinterpret_cast<const float4*>(hbase + (2 * node + 2) * MEM + k);
                        if (region == 0) { av.x += r4.x; av.y += r4.y; av.z += r4.z; av.w += r4.w; }
                        else             { av = r4; }
                    }
                }
            }
            As[kq + 0][row] = av.x;
            As[kq + 1][row] = av.y;
            As[kq + 2][row] = av.z;
            As[kq + 3][row] = av.w;
        }

        // ---- load B tile (W rows, transposed into Bs[k][n]) ----
        #pragma unroll
        for (int ld = 0; ld < 2; ld++) {
            int e   = tid * 2 + ld;
            int row = e >> 2;                // 0..127 (column within block; always valid)
            int kq  = (e & 3) << 2;
            int k   = k0 + kq;
            float4 bv = make_float4(0.f, 0.f, 0.f, 0.f);
            const float* src = Wsrc + (size_t)(wrow0 + row) * K + k;
            if (k + 3 < K) {
                bv = *reinterpret_cast<const float4*>(src);
            } else {
                float t[4] = {0.f, 0.f, 0.f, 0.f};
                #pragma unroll
                for (int q = 0; q < 4; q++)
                    if (k + q < K) t[q] = src[q];
                bv = make_float4(t[0], t[1], t[2], t[3]);
            }
            Bs[kq + 0][row] = bv.x;
            Bs[kq + 1][row] = bv.y;
            Bs[kq + 2][row] = bv.z;
            Bs[kq + 3][row] = bv.w;
        }

        __syncthreads();

        #pragma unroll
        for (int kk = 0; kk < BK; kk++) {
            float a[TM], b[TN];
            #pragma unroll
            for (int i = 0; i < TM; i++) a[i] = As[kk][ty * TM + i];
            #pragma unroll
            for (int j = 0; j < TN; j++) b[j] = Bs[kk][tx * TN + j];
            #pragma unroll
            for (int i = 0; i < TM; i++)
                #pragma unroll
                for (int j = 0; j < TN; j++)
                    acc[i][j] = fmaf(a[i], b[j], acc[i][j]);
        }

        __syncthreads();
    }

    // ---- epilogue ----
    float bsv[TN];
    if (MODE == 0) {
        #pragma unroll
        for (int j = 0; j < TN; j++) bsv[j] = g_bias[colBase + tx * TN + j];
    }
    #pragma unroll
    for (int i = 0; i < TM; i++) {
        int gm = m0 + ty * TM + i;
        if (gm >= M) continue;
        float* crow = Cbase + (size_t)gm * ldc + colBase + tx * TN;
        #pragma unroll
        for (int j = 0; j < TN; j += 4) {
            float4 v;
            v.x = acc[i][j + 0] + (MODE == 0 ? bsv[j + 0] : 0.f);
            v.y = acc[i][j + 1] + (MODE == 0 ? bsv[j + 1] : 0.f);
            v.z = acc[i][j + 2] + (MODE == 0 ? bsv[j + 2] : 0.f);
            v.w = acc[i][j + 3] + (MODE == 0 ? bsv[j + 3] : 0.f);
            *reinterpret_cast<float4*>(crow + j) = v;
        }
    }
}

// Leaves (level 15): c = sig(i)*tanh(u), h = sig(o)*tanh(c). fx region unused.
__global__ void leaf_kernel(float* __restrict__ c_out, float* __restrict__ h_out) {
    int node = LEAF_START + blockIdx.x;
    int m = threadIdx.x;
    const float* p = g_P + (size_t)node * XCOLS;
    float iv = sigmoidf_(p[m]);
    float ov = sigmoidf_(p[MEM + m]);
    float uv = tanhf(p[2 * MEM + m]);
    float cn = iv * uv;
    c_out[(size_t)node * MEM + m] = cn;
    h_out[(size_t)node * MEM + m] = ov * tanhf(cn);
}

// Internal-node combine for one level.
__global__ void combine_kernel(int start, float* __restrict__ c_out, float* __restrict__ h_out) {
    int r = blockIdx.x;
    int node = start + r;
    int m = threadIdx.x;
    const float* p = g_P + (size_t)node * XCOLS;
    const float* g = g_G + (size_t)r * GCOLS;
    float pi = p[m]           + g[m];
    float po = p[MEM + m]     + g[MEM + m];
    float pu = p[2 * MEM + m] + g[2 * MEM + m];
    float fx = p[IOU + m];                     // x@W_fx^T + b_fx + b_fh (folded)
    float fl = sigmoidf_(fx + g[IOU + m]);
    float fr = sigmoidf_(fx + g[IOU + MEM + m]);
    size_t li = (size_t)(2 * node + 1) * MEM + m;
    size_t ri = (size_t)(2 * node + 2) * MEM + m;
    float cn = sigmoidf_(pi) * tanhf(pu) + fl * c_out[li] + fr * c_out[ri];
    c_out[(size_t)node * MEM + m] = cn;
    h_out[(size_t)node * MEM + m] = sigmoidf_(po) * tanhf(cn);
}

extern "C" void kernel_launch(void* const* d_in, const int* in_sizes, int n_in,
                              void* d_out, int out_size) {
    const float* inputs = (const float*)d_in[0];
    const float* W_ioux = (const float*)d_in[1];
    const float* b_ioux = (const float*)d_in[2];
    const float* W_iouh = (const float*)d_in[3];
    const float* b_iouh = (const float*)d_in[4];
    const float* W_fx   = (const float*)d_in[5];
    const float* b_fx   = (const float*)d_in[6];
    const float* W_fh   = (const float*)d_in[7];
    const float* b_fh   = (const float*)d_in[8];

    float* c_out = (float*)d_out;                          // [N, 256]
    float* h_out = c_out + (size_t)NNODES * MEM;           // [N, 256]

    bias_prep<<<4, 256>>>(b_ioux, b_iouh, b_fx, b_fh);

    // x-projection: iou columns for ALL nodes
    {
        dim3 grid(IOU / BN, (NNODES + BM - 1) / BM);       // (6, 512)
        gemm_kernel<0><<<grid, 256>>>(NNODES, IN_DIM, 0,
                                      inputs, IN_DIM, nullptr, 0, W_ioux, W_fx);
    }
    // x-projection: fx columns only for internal nodes (leaves never read them)
    {
        dim3 grid(MEM / BN, (NINTERNAL + BM - 1) / BM);    // (2, 256)
        gemm_kernel<0><<<grid, 256>>>(NINTERNAL, IN_DIM, IOU,
                                      inputs, IN_DIM, nullptr, 0, W_ioux, W_fx);
    }

    // Leaves
    leaf_kernel<<<NLEAF, 256>>>(c_out, h_out);

    // Levels 14..0 (children always computed before parents)
    for (int d = 14; d >= 0; d--) {
        int size = 1 << d;
        int start = size - 1;
        dim3 grid(GCOLS / BN, (size + BM - 1) / BM);       // (10, ceil(size/128))
        gemm_kernel<1><<<grid, 256>>>(size, MEM, 0,
                                      nullptr, 0, h_out, start, W_iouh, W_fh);
        combine_kernel<<<size, 256>>>(start, c_out, h_out);
    }
}